// round 10
// baseline (speedup 1.0000x reference)
#include <cuda_runtime.h>
#include <cstdint>

// COO SpMM: out[dst] += val * x[src],  N=100K, E=1.6M, D=64.
//
//   1. memset per-node counters (400KB) + overflow counter
//   2. scatter: 4 edges/thread; the 4 positional atomics are issued
//      back-to-back (4-deep ATOMG pipeline) before the dependent stores.
//   3. main: one warp per node, TWO edges per iteration (unchanged R8):
//      lanes 0-15 -> edge i (float4 chunk/lane), lanes 16-31 -> edge i+1.
//   4. fixup: 1 block x 128, RED.128 for overflow edges (normally none)

static constexpr int D_FEAT = 64;
static constexpr int MAX_N  = 100000;
static constexpr int SLOTS  = 32;
static constexpr int OCAP   = 8192;

__device__ int  g_cnt[MAX_N + 1];            // [MAX_N] = overflow counter
__device__ int2 g_bucket[MAX_N * SLOTS];     // {src, float_as_int(val)} 25.6MB
__device__ int4 g_over[OCAP];                // {src, dst, valbits, 0}

// ---------------- phase 1: scatter into fixed buckets ----------------

__global__ void __launch_bounds__(256) scatter_kernel(
    const int*   __restrict__ edge_src,
    const int*   __restrict__ edge_dst,
    const float* __restrict__ edge_val,
    int n_edges)
{
    int i = blockIdx.x * blockDim.x + threadIdx.x;
    int e = i * 4;
    if (e + 3 < n_edges) {
        int4 s = __ldg(reinterpret_cast<const int4*>(edge_src) + i);
        int4 d = __ldg(reinterpret_cast<const int4*>(edge_dst) + i);
        int4 v = __ldg(reinterpret_cast<const int4*>(edge_val) + i);

        // Batch the 4 positional atomics: independent, pipeline 4-deep.
        int p0 = atomicAdd(&g_cnt[d.x], 1);
        int p1 = atomicAdd(&g_cnt[d.y], 1);
        int p2 = atomicAdd(&g_cnt[d.z], 1);
        int p3 = atomicAdd(&g_cnt[d.w], 1);

        if (p0 < SLOTS) g_bucket[(size_t)d.x * SLOTS + p0] = make_int2(s.x, v.x);
        else { int o = atomicAdd(&g_cnt[MAX_N], 1);
               if (o < OCAP) g_over[o] = make_int4(s.x, d.x, v.x, 0); }
        if (p1 < SLOTS) g_bucket[(size_t)d.y * SLOTS + p1] = make_int2(s.y, v.y);
        else { int o = atomicAdd(&g_cnt[MAX_N], 1);
               if (o < OCAP) g_over[o] = make_int4(s.y, d.y, v.y, 0); }
        if (p2 < SLOTS) g_bucket[(size_t)d.z * SLOTS + p2] = make_int2(s.z, v.z);
        else { int o = atomicAdd(&g_cnt[MAX_N], 1);
               if (o < OCAP) g_over[o] = make_int4(s.z, d.z, v.z, 0); }
        if (p3 < SLOTS) g_bucket[(size_t)d.w * SLOTS + p3] = make_int2(s.w, v.w);
        else { int o = atomicAdd(&g_cnt[MAX_N], 1);
               if (o < OCAP) g_over[o] = make_int4(s.w, d.w, v.w, 0); }
    } else {
        for (; e < n_edges; e++) {
            int dst = __ldg(edge_dst + e);
            int src = __ldg(edge_src + e);
            int vb  = __float_as_int(__ldg(edge_val + e));
            int pos = atomicAdd(&g_cnt[dst], 1);
            if (pos < SLOTS) {
                g_bucket[(size_t)dst * SLOTS + pos] = make_int2(src, vb);
            } else {
                int o = atomicAdd(&g_cnt[MAX_N], 1);
                if (o < OCAP) g_over[o] = make_int4(src, dst, vb, 0);
            }
        }
    }
}

// ---------------- phase 2: accumulate, one warp per node, 2 edges/iter -----

__global__ void __launch_bounds__(256) spmm_csr_kernel(
    const float* __restrict__ x,
    float*       __restrict__ out,
    int n_nodes)
{
    int wid   = (blockIdx.x * blockDim.x + threadIdx.x) >> 5;
    int lane  = threadIdx.x & 31;
    int half  = lane >> 4;     // 0: even edges, 1: odd edges
    int hlane = lane & 15;     // float4 chunk within the row
    if (wid >= n_nodes) return;

    int cnt = g_cnt[wid];
    if (cnt > SLOTS) cnt = SLOTS;

    // Coalesced 256B bucket-row load: one entry per lane.
    int2 entry = __ldg(g_bucket + (size_t)wid * SLOTS + lane);

    const float4* xf4 = reinterpret_cast<const float4*>(x);
    float4 acc = make_float4(0.f, 0.f, 0.f, 0.f);

    // Two edges per iteration; gathers independent of each other.
    #pragma unroll 4
    for (int i = 0; i < cnt; i += 2) {
        int idx = i + half;                         // <= 31 always
        int   src = __shfl_sync(0xffffffffu, entry.x, idx);
        float val = __int_as_float(__shfl_sync(0xffffffffu, entry.y, idx));
        if (idx < cnt) {
            float4 v = __ldg(xf4 + (size_t)src * 16 + hlane);
            acc.x = fmaf(v.x, val, acc.x);
            acc.y = fmaf(v.y, val, acc.y);
            acc.z = fmaf(v.z, val, acc.z);
            acc.w = fmaf(v.w, val, acc.w);
        }
    }

    // Combine the two half-warp partial sums.
    acc.x += __shfl_xor_sync(0xffffffffu, acc.x, 16);
    acc.y += __shfl_xor_sync(0xffffffffu, acc.y, 16);
    acc.z += __shfl_xor_sync(0xffffffffu, acc.z, 16);
    acc.w += __shfl_xor_sync(0xffffffffu, acc.w, 16);

    if (half == 0) {
        reinterpret_cast<float4*>(out)[(size_t)wid * 16 + hlane] = acc;
    }
}

// ---------------- phase 3: overflow fixup (1 block, normally empty) --------

__global__ void __launch_bounds__(128) fixup_kernel(
    const float* __restrict__ x,
    float*       __restrict__ out)
{
    int ocnt = g_cnt[MAX_N];
    if (ocnt > OCAP) ocnt = OCAP;
    int total = ocnt * 16;

    for (int t = threadIdx.x; t < total; t += blockDim.x) {
        int e = t >> 4;
        int c = t & 15;
        int4 rec = g_over[e];
        float val = __int_as_float(rec.z);
        float4 v = __ldg(reinterpret_cast<const float4*>(
                             x + (size_t)rec.x * D_FEAT) + c);
        float4 r;
        r.x = v.x * val; r.y = v.y * val; r.z = v.z * val; r.w = v.w * val;
        float* o = out + (size_t)rec.y * D_FEAT + c * 4;
        asm volatile("red.global.add.v4.f32 [%0], {%1, %2, %3, %4};"
                     :: "l"(o), "f"(r.x), "f"(r.y), "f"(r.z), "f"(r.w)
                     : "memory");
    }
}

// ---------------- launch ----------------

extern "C" void kernel_launch(void* const* d_in, const int* in_sizes, int n_in,
                              void* d_out, int out_size) {
    const float* x        = (const float*)d_in[0];
    const float* edge_val = (const float*)d_in[1];
    const int*   edge_src = (const int*)d_in[2];
    const int*   edge_dst = (const int*)d_in[3];
    float*       out      = (float*)d_out;

    int n_edges = in_sizes[1];
    int n_nodes = out_size / D_FEAT;

    void* cnt_ptr = nullptr;
    cudaGetSymbolAddress(&cnt_ptr, g_cnt);
    cudaMemsetAsync(cnt_ptr, 0, (MAX_N + 1) * sizeof(int), 0);

    int sc_threads = (n_edges + 3) / 4;
    scatter_kernel<<<(sc_threads + 255) / 256, 256>>>(edge_src, edge_dst,
                                                      edge_val, n_edges);

    int warps_per_block = 256 / 32;
    int grid = (n_nodes + warps_per_block - 1) / warps_per_block;
    spmm_csr_kernel<<<grid, 256>>>(x, out, n_nodes);

    fixup_kernel<<<1, 128>>>(x, out);
}

// round 11
// speedup vs baseline: 1.0656x; 1.0656x over previous
#include <cuda_runtime.h>
#include <cstdint>

// COO SpMM: out[dst] += val * x[src],  N=100K, E=1.6M, D=64.
//
// 3-node graph:
//   1. scatter: 4 edges/thread; pos = atomicAdd(cnt[dst]);
//      bucket[dst*32+pos] = {src,val}; overflow -> side list.
//      (counters are zeroed by the PREVIOUS call's clean_fix; device
//       globals start zero, so the first call is clean too.)
//   2. main: one warp per node, two edges/iter (lanes 0-15 edge i,
//      lanes 16-31 edge i+1), BRANCH-FREE gather: unconditional LDG.128
//      with clamped src + SEL-zeroed multiplier -> ptxas can front-batch
//      loads across the unroll (higher MLP).
//   3. clean_fix: zero all counters for next replay; block 0 also applies
//      overflow edges to out via RED.128 (normally none).

static constexpr int D_FEAT = 64;
static constexpr int MAX_N  = 100000;
static constexpr int SLOTS  = 32;
static constexpr int OCAP   = 8192;

__device__ int  g_cnt[MAX_N + 1];            // [MAX_N] = overflow counter
__device__ int2 g_bucket[MAX_N * SLOTS];     // {src, float_as_int(val)} 25.6MB
__device__ int4 g_over[OCAP];                // {src, dst, valbits, 0}

// ---------------- phase 1: scatter into fixed buckets ----------------

__device__ __forceinline__ void scatter_one(int src, int dst, int valbits) {
    int pos = atomicAdd(&g_cnt[dst], 1);
    if (pos < SLOTS) {
        g_bucket[(size_t)dst * SLOTS + pos] = make_int2(src, valbits);
    } else {
        int o = atomicAdd(&g_cnt[MAX_N], 1);
        if (o < OCAP) g_over[o] = make_int4(src, dst, valbits, 0);
    }
}

__global__ void __launch_bounds__(256) scatter_kernel(
    const int*   __restrict__ edge_src,
    const int*   __restrict__ edge_dst,
    const float* __restrict__ edge_val,
    int n_edges)
{
    int i = blockIdx.x * blockDim.x + threadIdx.x;
    int e = i * 4;
    if (e + 3 < n_edges) {
        int4 s = __ldg(reinterpret_cast<const int4*>(edge_src) + i);
        int4 d = __ldg(reinterpret_cast<const int4*>(edge_dst) + i);
        int4 v = __ldg(reinterpret_cast<const int4*>(edge_val) + i);
        scatter_one(s.x, d.x, v.x);
        scatter_one(s.y, d.y, v.y);
        scatter_one(s.z, d.z, v.z);
        scatter_one(s.w, d.w, v.w);
    } else {
        for (; e < n_edges; e++) {
            scatter_one(__ldg(edge_src + e), __ldg(edge_dst + e),
                        __float_as_int(__ldg(edge_val + e)));
        }
    }
}

// ---------------- phase 2: accumulate, one warp per node, 2 edges/iter -----

__global__ void __launch_bounds__(256) spmm_csr_kernel(
    const float* __restrict__ x,
    float*       __restrict__ out,
    int n_nodes)
{
    int wid   = (blockIdx.x * blockDim.x + threadIdx.x) >> 5;
    int lane  = threadIdx.x & 31;
    int half  = lane >> 4;     // 0: even edges, 1: odd edges
    int hlane = lane & 15;     // float4 chunk within the row
    if (wid >= n_nodes) return;

    int cnt = g_cnt[wid];
    if (cnt > SLOTS) cnt = SLOTS;

    // Coalesced 256B bucket-row load: one entry per lane.
    int2 entry = __ldg(g_bucket + (size_t)wid * SLOTS + lane);

    const float4* xf4 = reinterpret_cast<const float4*>(x);
    float4 acc = make_float4(0.f, 0.f, 0.f, 0.f);

    // Branch-free body: unconditional LDG (clamped src) + SEL-zeroed scale.
    // All loads in an unroll group are independent -> front-batched.
    #pragma unroll 4
    for (int i = 0; i < cnt; i += 2) {
        int idx = i + half;                         // <= 31 always
        int   src = __shfl_sync(0xffffffffu, entry.x, idx);
        float val = __int_as_float(__shfl_sync(0xffffffffu, entry.y, idx));
        unsigned us = (unsigned)src;
        if (us >= (unsigned)n_nodes) us = 0u;       // clamp stale garbage (SEL)
        float m = (idx < cnt) ? val : 0.0f;         // SEL, no branch
        float4 v = __ldg(xf4 + (size_t)us * 16 + hlane);
        acc.x = fmaf(v.x, m, acc.x);
        acc.y = fmaf(v.y, m, acc.y);
        acc.z = fmaf(v.z, m, acc.z);
        acc.w = fmaf(v.w, m, acc.w);
    }

    // Combine the two half-warp partial sums.
    acc.x += __shfl_xor_sync(0xffffffffu, acc.x, 16);
    acc.y += __shfl_xor_sync(0xffffffffu, acc.y, 16);
    acc.z += __shfl_xor_sync(0xffffffffu, acc.z, 16);
    acc.w += __shfl_xor_sync(0xffffffffu, acc.w, 16);

    if (half == 0) {
        reinterpret_cast<float4*>(out)[(size_t)wid * 16 + hlane] = acc;
    }
}

// ------- phase 3: zero counters for next replay + overflow fixup -----------

__global__ void __launch_bounds__(256) clean_fix_kernel(
    const float* __restrict__ x,
    float*       __restrict__ out)
{
    // zero per-node counters (grid-stride over MAX_N ints)
    int stride = gridDim.x * blockDim.x;
    for (int i = blockIdx.x * blockDim.x + threadIdx.x; i < MAX_N; i += stride)
        g_cnt[i] = 0;

    // block 0: apply overflow edges, then zero the overflow counter
    if (blockIdx.x == 0) {
        int ocnt = g_cnt[MAX_N];
        if (ocnt > OCAP) ocnt = OCAP;
        __syncthreads();
        if (threadIdx.x == 0) g_cnt[MAX_N] = 0;

        int total = ocnt * 16;
        for (int t = threadIdx.x; t < total; t += blockDim.x) {
            int e = t >> 4;
            int c = t & 15;
            int4 rec = g_over[e];
            float val = __int_as_float(rec.z);
            float4 v = __ldg(reinterpret_cast<const float4*>(
                                 x + (size_t)rec.x * D_FEAT) + c);
            float4 r;
            r.x = v.x * val; r.y = v.y * val; r.z = v.z * val; r.w = v.w * val;
            float* o = out + (size_t)rec.y * D_FEAT + c * 4;
            asm volatile("red.global.add.v4.f32 [%0], {%1, %2, %3, %4};"
                         :: "l"(o), "f"(r.x), "f"(r.y), "f"(r.z), "f"(r.w)
                         : "memory");
        }
    }
}

// ---------------- launch ----------------

extern "C" void kernel_launch(void* const* d_in, const int* in_sizes, int n_in,
                              void* d_out, int out_size) {
    const float* x        = (const float*)d_in[0];
    const float* edge_val = (const float*)d_in[1];
    const int*   edge_src = (const int*)d_in[2];
    const int*   edge_dst = (const int*)d_in[3];
    float*       out      = (float*)d_out;

    int n_edges = in_sizes[1];
    int n_nodes = out_size / D_FEAT;

    int sc_threads = (n_edges + 3) / 4;
    scatter_kernel<<<(sc_threads + 255) / 256, 256>>>(edge_src, edge_dst,
                                                      edge_val, n_edges);

    int warps_per_block = 256 / 32;
    int grid = (n_nodes + warps_per_block - 1) / warps_per_block;
    spmm_csr_kernel<<<grid, 256>>>(x, out, n_nodes);

    clean_fix_kernel<<<148, 256>>>(x, out);
}